// round 12
// baseline (speedup 1.0000x reference)
#include <cuda_runtime.h>
#include <cuda_bf16.h>
#include <cstdint>

// Problem constants
#define Bb 8
#define Cc 64
#define Nn 4096
#define BN (Bb * Nn)
#define KSPLIT 4
#define KPC (Nn / KSPLIT)       // 1024 keys per CTA
#define CHK 256                 // keys per chunk
#define NCHK (KPC / CHK)        // 4 chunks
#define BCN ((size_t)Bb * Cc * Nn)
#define LOG2E 1.4426950408889634f
#define SHIFT 10.0f             // p' = 2^(s-SHIFT); cancels in v = num/den

// Scratch
__device__ uint32_t d_fpk[(size_t)BN * 8];        // per key: fh0..3, fl0..3 (bf16x2)
__device__ unsigned short d_hT[8 * (size_t)BN];   // fp16, [emb][b*Nn + n]
__device__ float d_g[(size_t)BN * 8];             // pre-scaled by log2e
__device__ float d_pacc[(size_t)KSPLIT * BN * 8];
__device__ float d_pden[(size_t)KSPLIT * BN];

// ---------------- helpers ----------------
__device__ __forceinline__ float ex2f(float x) {
    float y; asm("ex2.approx.f32 %0, %1;" : "=f"(y) : "f"(x)); return y;
}
// fp32 exp2 via FMA pipe: magic-add round + deg-4 poly + exponent splice.
// Valid for x in ~[-100, 60]; abs rel err ~4e-5.
__device__ __forceinline__ float exp2poly(float s) {
    const float MAGIC = 12582912.f;          // 2^23 + 2^22
    const float t = s + MAGIC;               // round(s) in low mantissa bits
    const float u = t - MAGIC;
    const float f = s - u;                   // f in [-0.5, 0.5]
    float p = fmaf(f, 0.00961812910f, 0.0555041087f);
    p = fmaf(f, p, 0.240226507f);
    p = fmaf(f, p, 0.693147181f);
    p = fmaf(f, p, 1.0f);
    const uint32_t ib = __float_as_uint(p) + (__float_as_uint(t) << 23);
    return __uint_as_float(ib);
}
// Dekker split of 2 floats into bf16 hi-pair word (lo16=a, hi16=b) and lo-pair word
__device__ __forceinline__ void pack_split(float a, float b, uint32_t& hw, uint32_t& lw) {
    uint32_t h;
    asm("cvt.rn.bf16x2.f32 %0, %1, %2;" : "=r"(h) : "f"(b), "f"(a));
    const float ah = __uint_as_float(h << 16);
    const float bh = __uint_as_float(h & 0xFFFF0000u);
    const float al = a - ah, bl = b - bh;
    uint32_t l;
    asm("cvt.rn.bf16x2.f32 %0, %1, %2;" : "=r"(l) : "f"(bl), "f"(al));
    hw = h; lw = l;
}
// fp16x2 pack with satfinite; lo16=a, hi16=b
__device__ __forceinline__ uint32_t pkf16s(float a, float b) {
    uint32_t r;
    asm("cvt.rn.satfinite.f16x2.f32 %0, %1, %2;" : "=r"(r) : "f"(b), "f"(a));
    return r;
}
__device__ __forceinline__ unsigned short f2h(float a) {
    unsigned short r;
    asm("cvt.rn.f16.f32 %0, %1;" : "=h"(r) : "f"(a));
    return r;
}
// m16n8k16 bf16 MMA, row.col, f32 accumulate (D += A*B)
__device__ __forceinline__ void mma16816(float* d, const uint32_t* a,
                                         uint32_t b0, uint32_t b1) {
    asm volatile("mma.sync.aligned.m16n8k16.row.col.f32.bf16.bf16.f32 "
        "{%0,%1,%2,%3}, {%4,%5,%6,%7}, {%8,%9}, {%0,%1,%2,%3};"
        : "+f"(d[0]), "+f"(d[1]), "+f"(d[2]), "+f"(d[3])
        : "r"(a[0]), "r"(a[1]), "r"(a[2]), "r"(a[3]), "r"(b0), "r"(b1));
}
// m16n8k16 fp16 MMA, row.col, f32 accumulate
__device__ __forceinline__ void mma16816h(float* d, const uint32_t* a,
                                          uint32_t b0, uint32_t b1) {
    asm volatile("mma.sync.aligned.m16n8k16.row.col.f32.f16.f16.f32 "
        "{%0,%1,%2,%3}, {%4,%5,%6,%7}, {%8,%9}, {%0,%1,%2,%3};"
        : "+f"(d[0]), "+f"(d[1]), "+f"(d[2]), "+f"(d[3])
        : "r"(a[0]), "r"(a[1]), "r"(a[2]), "r"(a[3]), "r"(b0), "r"(b1));
}

// ---------------- Kernel A: projections f, g, h (pre-packed outputs) ------
// grid (Nn/128, Bb), block 256: 128 px x 2 channel-halves, smem combine.
__global__ __launch_bounds__(256) void proj_kernel(
    const float* __restrict__ x,
    const float* __restrict__ Wk, const float* __restrict__ bk,
    const float* __restrict__ Wq, const float* __restrict__ bq,
    const float* __restrict__ Wv, const float* __restrict__ bv)
{
    __shared__ float wks[512], wqs[512], wvs[512];
    __shared__ float red[24][128];      // part 1 stages its partials
    const int t = threadIdx.x, px = t & 127, part = t >> 7;
    const int b = blockIdx.y;
    const int n = blockIdx.x * 128 + px;

    // front-load x (32 independent LDGs)
    float xv[32];
    const float* xp = &x[((size_t)b * 64 + part * 32) * Nn + n];
    #pragma unroll
    for (int i = 0; i < 32; i++) xv[i] = xp[(size_t)i * Nn];

    for (int i = t; i < 512; i += 256) {
        wks[i] = Wk[i];
        wqs[i] = Wq[i] * LOG2E;
        wvs[i] = Wv[i];
    }
    __syncthreads();

    float f[8], g[8], h[8];
    #pragma unroll
    for (int e = 0; e < 8; e++) { f[e] = 0.f; g[e] = 0.f; h[e] = 0.f; }

    #pragma unroll
    for (int i = 0; i < 32; i++) {
        const int c = part * 32 + i;
        #pragma unroll
        for (int e = 0; e < 8; e++) {
            f[e] = fmaf(wks[e * 64 + c], xv[i], f[e]);
            g[e] = fmaf(wqs[e * 64 + c], xv[i], g[e]);
            h[e] = fmaf(wvs[e * 64 + c], xv[i], h[e]);
        }
    }
    if (part == 1) {
        #pragma unroll
        for (int e = 0; e < 8; e++) {
            red[e][px]      = f[e];
            red[8 + e][px]  = g[e];
            red[16 + e][px] = h[e];
        }
    }
    __syncthreads();
    if (part == 0) {
        #pragma unroll
        for (int e = 0; e < 8; e++) {
            f[e] += red[e][px]      + bk[e];
            g[e] += red[8 + e][px]  + bq[e] * LOG2E;
            h[e] += red[16 + e][px] + bv[e];
        }
        const size_t bn = (size_t)b * Nn + n;
        // F: bf16 Dekker pre-pack
        uint32_t h0,l0,h1,l1,h2,l2,h3,l3;
        pack_split(f[0], f[1], h0, l0);
        pack_split(f[2], f[3], h1, l1);
        pack_split(f[4], f[5], h2, l2);
        pack_split(f[6], f[7], h3, l3);
        uint4* fp = (uint4*)&d_fpk[bn * 8];
        fp[0] = make_uint4(h0, h1, h2, h3);
        fp[1] = make_uint4(l0, l1, l2, l3);
        // H: fp16 transposed
        #pragma unroll
        for (int e = 0; e < 8; e++)
            d_hT[(size_t)e * BN + bn] = f2h(h[e]);
        // G: f32
        float4* gp = (float4*)&d_g[bn * 8];
        gp[0] = make_float4(g[0], g[1], g[2], g[3]);
        gp[1] = make_float4(g[4], g[5], g[6], g[7]);
    }
}

// ---------------- Kernel B: FA2-style HMMA attention ----------------------
// grid (KSPLIT, Nn/128, Bb), block 128 (4 warps, 32 queries each).
// Hybrid exp: 2 of 8 via FMA-pipe polynomial, 6 via MUFU ex2.
__global__ __launch_bounds__(128) void attn_kernel()
{
    __shared__ __align__(16) uint32_t s_fh[2][CHK * 4];   // f_hi bf16x2: [key][4]
    __shared__ __align__(16) uint32_t s_fl[2][CHK * 4];   // f_lo
    __shared__ __align__(16) uint32_t s_hT[2][8 * 132];   // H^T fp16x2: 8 rows, 132 u32 stride

    const int t = threadIdx.x, wid = t >> 5, lane = t & 31;
    const int ks = blockIdx.x, qt = blockIdx.y, b = blockIdx.z;
    const int kbase = ks * KPC;
    const int r = lane >> 2, c2 = (lane & 3) * 2;
    const uint32_t ONES = 0x3C003C00u;   // fp16x2 {1,1}

    // G A-fragments (once): A[16q x 16] = [g_hi(8) | g_lo(8)] bf16
    uint32_t aG[2][4];
    #pragma unroll
    for (int mt = 0; mt < 2; mt++) {
        #pragma unroll
        for (int hh = 0; hh < 2; hh++) {
            const int q = qt * 128 + wid * 32 + mt * 16 + r + hh * 8;
            const float2 gv = *(const float2*)&d_g[((size_t)b * Nn + q) * 8 + c2];
            uint32_t hw, lw;
            pack_split(gv.x, gv.y, hw, lw);
            aG[mt][hh]     = hw;
            aG[mt][2 + hh] = lw;
        }
    }

    float vacc[2][4] = {{0.f,0.f,0.f,0.f},{0.f,0.f,0.f,0.f}};
    float dacc[2][4] = {{0.f,0.f,0.f,0.f},{0.f,0.f,0.f,0.f}};

    auto load_chunk = [&](int ch, int buf) {
        const size_t base = (size_t)b * Nn + kbase + ch * CHK;
        // F: keys t, t+128 — straight uint4 copies
        #pragma unroll
        for (int kk = 0; kk < 2; kk++) {
            const int key = t + kk * 128;
            const uint4* src = (const uint4*)&d_fpk[(base + key) * 8];
            *(uint4*)&s_fh[buf][key * 4] = src[0];
            *(uint4*)&s_fl[buf][key * 4] = src[1];
        }
        // H^T: 8 rows x 128 u32; thread t -> row t>>4, words (t&15)*8 .. +8
        {
            const int d = t >> 4, w = (t & 15) * 8;
            const uint4* hs = (const uint4*)((const uint32_t*)d_hT +
                                             (((size_t)d * BN + base) >> 1) + w);
            *(uint4*)&s_hT[buf][d * 132 + w]     = hs[0];
            *(uint4*)&s_hT[buf][d * 132 + w + 4] = hs[1];
        }
    };

    auto compute = [&](int buf) {
        #pragma unroll
        for (int g = 0; g < 16; g++) {         // 16-key groups
            #pragma unroll
            for (int mt = 0; mt < 2; mt++) {
                // S: two n8 tiles, exact via bf16 hi+lo; acc pre-biased -SHIFT
                float s[8] = {-SHIFT,-SHIFT,-SHIFT,-SHIFT,-SHIFT,-SHIFT,-SHIFT,-SHIFT};
                #pragma unroll
                for (int nt = 0; nt < 2; nt++) {
                    const int key = g * 16 + nt * 8 + r;
                    const uint32_t bh = s_fh[buf][key * 4 + (lane & 3)];
                    const uint32_t bl = s_fl[buf][key * 4 + (lane & 3)];
                    mma16816(&s[nt * 4], aG[mt], bh, bh);  // (gh+gl)*fh
                    mma16816(&s[nt * 4], aG[mt], bl, bl);  // (gh+gl)*fl
                }
                // hybrid exp: 2 on FMA pipe (poly), 6 on MUFU
                float p[8];
                p[0] = exp2poly(s[0]);
                p[1] = exp2poly(s[1]);
                #pragma unroll
                for (int j = 2; j < 8; j++) p[j] = ex2f(s[j]);
                // P A-fragment, fp16 satfinite
                uint32_t ap[4];
                ap[0] = pkf16s(p[0], p[1]);
                ap[1] = pkf16s(p[2], p[3]);
                ap[2] = pkf16s(p[4], p[5]);
                ap[3] = pkf16s(p[6], p[7]);
                // V: single fp16 MMA over 16 keys
                const int kw = g * 8 + (lane & 3);
                const uint32_t b0 = s_hT[buf][r * 132 + kw];
                const uint32_t b1 = s_hT[buf][r * 132 + kw + 4];
                mma16816h(vacc[mt], ap, b0, b1);
                // den: P row-sum via ones-B MMA (tensor pipe)
                mma16816h(dacc[mt], ap, ONES, ONES);
            }
        }
    };

    load_chunk(0, 0);
    __syncthreads();
    for (int ch = 0; ch < NCHK; ch++) {
        if (ch + 1 < NCHK) load_chunk(ch + 1, (ch + 1) & 1);  // LDGs overlap compute
        compute(ch & 1);
        __syncthreads();
    }

    // Epilogue: dacc holds full row-sums (all cols identical)
    const size_t base = ((size_t)ks * Bb + b) * Nn;
    #pragma unroll
    for (int mt = 0; mt < 2; mt++) {
        #pragma unroll
        for (int hh = 0; hh < 2; hh++) {
            const int q = qt * 128 + wid * 32 + mt * 16 + r + hh * 8;
            *(float2*)&d_pacc[(base + q) * 8 + c2] =
                make_float2(vacc[mt][2 * hh], vacc[mt][2 * hh + 1]);
            if ((lane & 3) == 0) d_pden[base + q] = dacc[mt][2 * hh];
        }
    }
}

// ---------------- Kernel C: combine splits, Wo projection, y ---------------
// grid (Nn/128, Bb), block 256: both halves combine 2 splits each.
__global__ __launch_bounds__(256) void out_kernel(
    const float* __restrict__ x,
    const float* __restrict__ Wo, const float* __restrict__ bo,
    const float* __restrict__ gamma, float* __restrict__ out)
{
    __shared__ float vs[8 * 128];
    __shared__ float red2[9][128];
    __shared__ float wos[512], bos[64];
    const int t = threadIdx.x, px = t & 127, half = t >> 7;
    const int b = blockIdx.y;
    const int m = blockIdx.x * 128 + px;

    for (int i = t; i < 512; i += 256) wos[i] = Wo[i];
    if (t < 64) bos[t] = bo[t];

    float acc[8] = {0, 0, 0, 0, 0, 0, 0, 0};
    float den = 0.0f;
    #pragma unroll
    for (int si = 0; si < 2; si++) {
        const int s = half * 2 + si;
        const size_t base = ((size_t)s * Bb + b) * Nn + m;
        const float4* pp = (const float4*)&d_pacc[base * 8];
        const float4 a0 = pp[0], a1 = pp[1];
        acc[0] += a0.x; acc[1] += a0.y; acc[2] += a0.z; acc[3] += a0.w;
        acc[4] += a1.x; acc[5] += a1.y; acc[6] += a1.z; acc[7] += a1.w;
        den += d_pden[base];
    }
    if (half == 1) {
        #pragma unroll
        for (int e = 0; e < 8; e++) red2[e][px] = acc[e];
        red2[8][px] = den;
    }
    __syncthreads();
    if (half == 0) {
        den += red2[8][px];
        const float inv = 1.0f / den;
        #pragma unroll
        for (int e = 0; e < 8; e++)
            vs[e * 128 + px] = (acc[e] + red2[e][px]) * inv;
    }
    __syncthreads();

    const float gam = gamma[0];
    #pragma unroll 4
    for (int ci = 0; ci < 32; ci++) {
        const int c = half * 32 + ci;
        float o = bos[c];
        #pragma unroll
        for (int e = 0; e < 8; e++) o = fmaf(wos[c * 8 + e], vs[e * 128 + px], o);
        const size_t idx = ((size_t)b * 64 + c) * Nn + m;
        out[BCN + idx] = o;
        out[idx]       = fmaf(gam, o, x[idx]);
    }
    if (b == 0 && m == 0 && half == 0) out[2 * BCN] = gam;
}

// ---------------- Launch ----------------------------------------------------
extern "C" void kernel_launch(void* const* d_in, const int* in_sizes, int n_in,
                              void* d_out, int out_size)
{
    const float* x     = (const float*)d_in[0];
    const float* Wk    = (const float*)d_in[1];
    const float* bk    = (const float*)d_in[2];
    const float* Wq    = (const float*)d_in[3];
    const float* bq    = (const float*)d_in[4];
    const float* Wv    = (const float*)d_in[5];
    const float* bv    = (const float*)d_in[6];
    const float* Wo    = (const float*)d_in[7];
    const float* bo    = (const float*)d_in[8];
    const float* gamma = (const float*)d_in[9];
    float* out = (float*)d_out;

    proj_kernel<<<dim3(Nn / 128, Bb), 256>>>(x, Wk, bk, Wq, bq, Wv, bv);
    attn_kernel<<<dim3(KSPLIT, Nn / 128, Bb), 128>>>();
    out_kernel<<<dim3(Nn / 128, Bb), 256>>>(x, Wo, bo, gamma, out);
}

// round 13
// speedup vs baseline: 1.1466x; 1.1466x over previous
#include <cuda_runtime.h>
#include <cuda_bf16.h>
#include <cstdint>

// Problem constants
#define Bb 8
#define Cc 64
#define Nn 4096
#define BN (Bb * Nn)
#define KSPLIT 4
#define KPC (Nn / KSPLIT)       // 1024 keys per CTA
#define CHK 256                 // keys per chunk
#define NCHK (KPC / CHK)        // 4 chunks
#define BCN ((size_t)Bb * Cc * Nn)
#define LOG2E 1.4426950408889634f
#define SHIFT 10.0f             // p' = 2^(s-SHIFT); cancels in v = num/den

// Scratch
__device__ uint32_t d_fpk[(size_t)BN * 8];        // per key: fh0..3, fl0..3 (bf16x2)
__device__ unsigned short d_hT[8 * (size_t)BN];   // fp16, [emb][b*Nn + n]
__device__ float d_g[(size_t)BN * 8];             // pre-scaled by log2e
__device__ float d_pacc[(size_t)KSPLIT * BN * 8];
__device__ float d_pden[(size_t)KSPLIT * BN];

// ---------------- helpers ----------------
__device__ __forceinline__ float ex2f(float x) {
    float y; asm("ex2.approx.f32 %0, %1;" : "=f"(y) : "f"(x)); return y;
}
// Dekker split of 2 floats into bf16 hi-pair word (lo16=a, hi16=b) and lo-pair word
__device__ __forceinline__ void pack_split(float a, float b, uint32_t& hw, uint32_t& lw) {
    uint32_t h;
    asm("cvt.rn.bf16x2.f32 %0, %1, %2;" : "=r"(h) : "f"(b), "f"(a));
    const float ah = __uint_as_float(h << 16);
    const float bh = __uint_as_float(h & 0xFFFF0000u);
    const float al = a - ah, bl = b - bh;
    uint32_t l;
    asm("cvt.rn.bf16x2.f32 %0, %1, %2;" : "=r"(l) : "f"(bl), "f"(al));
    hw = h; lw = l;
}
// fp16x2 pack with satfinite; lo16=a, hi16=b
__device__ __forceinline__ uint32_t pkf16s(float a, float b) {
    uint32_t r;
    asm("cvt.rn.satfinite.f16x2.f32 %0, %1, %2;" : "=r"(r) : "f"(b), "f"(a));
    return r;
}
__device__ __forceinline__ unsigned short f2h(float a) {
    unsigned short r;
    asm("cvt.rn.f16.f32 %0, %1;" : "=h"(r) : "f"(a));
    return r;
}
// m16n8k16 bf16 MMA, row.col, f32 accumulate (D += A*B)
__device__ __forceinline__ void mma16816(float* d, const uint32_t* a,
                                         uint32_t b0, uint32_t b1) {
    asm volatile("mma.sync.aligned.m16n8k16.row.col.f32.bf16.bf16.f32 "
        "{%0,%1,%2,%3}, {%4,%5,%6,%7}, {%8,%9}, {%0,%1,%2,%3};"
        : "+f"(d[0]), "+f"(d[1]), "+f"(d[2]), "+f"(d[3])
        : "r"(a[0]), "r"(a[1]), "r"(a[2]), "r"(a[3]), "r"(b0), "r"(b1));
}
// m16n8k16 fp16 MMA, row.col, f32 accumulate
__device__ __forceinline__ void mma16816h(float* d, const uint32_t* a,
                                          uint32_t b0, uint32_t b1) {
    asm volatile("mma.sync.aligned.m16n8k16.row.col.f32.f16.f16.f32 "
        "{%0,%1,%2,%3}, {%4,%5,%6,%7}, {%8,%9}, {%0,%1,%2,%3};"
        : "+f"(d[0]), "+f"(d[1]), "+f"(d[2]), "+f"(d[3])
        : "r"(a[0]), "r"(a[1]), "r"(a[2]), "r"(a[3]), "r"(b0), "r"(b1));
}

// ---------------- Kernel A: projections f, g, h (pre-packed outputs) ------
// grid (Nn/64, Bb), block 256: 64 px x 4 channel-parts, smem combine.
__global__ __launch_bounds__(256) void proj_kernel(
    const float* __restrict__ x,
    const float* __restrict__ Wk, const float* __restrict__ bk,
    const float* __restrict__ Wq, const float* __restrict__ bq,
    const float* __restrict__ Wv, const float* __restrict__ bv)
{
    __shared__ float wks[512], wqs[512], wvs[512];
    __shared__ float red[3][24][64];    // parts 1..3 stage their partials
    const int t = threadIdx.x, px = t & 63, part = t >> 6;
    const int b = blockIdx.y;
    const int n = blockIdx.x * 64 + px;

    // front-load x (16 independent LDGs per thread)
    float xv[16];
    const float* xp = &x[((size_t)b * 64 + part * 16) * Nn + n];
    #pragma unroll
    for (int i = 0; i < 16; i++) xv[i] = xp[(size_t)i * Nn];

    for (int i = t; i < 512; i += 256) {
        wks[i] = Wk[i];
        wqs[i] = Wq[i] * LOG2E;
        wvs[i] = Wv[i];
    }
    __syncthreads();

    float f[8], g[8], h[8];
    #pragma unroll
    for (int e = 0; e < 8; e++) { f[e] = 0.f; g[e] = 0.f; h[e] = 0.f; }

    #pragma unroll
    for (int i = 0; i < 16; i++) {
        const int c = part * 16 + i;
        #pragma unroll
        for (int e = 0; e < 8; e++) {
            f[e] = fmaf(wks[e * 64 + c], xv[i], f[e]);
            g[e] = fmaf(wqs[e * 64 + c], xv[i], g[e]);
            h[e] = fmaf(wvs[e * 64 + c], xv[i], h[e]);
        }
    }
    if (part > 0) {
        #pragma unroll
        for (int e = 0; e < 8; e++) {
            red[part - 1][e][px]      = f[e];
            red[part - 1][8 + e][px]  = g[e];
            red[part - 1][16 + e][px] = h[e];
        }
    }
    __syncthreads();
    if (part == 0) {
        #pragma unroll
        for (int e = 0; e < 8; e++) {
            f[e] += red[0][e][px]      + red[1][e][px]      + red[2][e][px]      + bk[e];
            g[e] += red[0][8 + e][px]  + red[1][8 + e][px]  + red[2][8 + e][px]  + bq[e] * LOG2E;
            h[e] += red[0][16 + e][px] + red[1][16 + e][px] + red[2][16 + e][px] + bv[e];
        }
        const size_t bn = (size_t)b * Nn + n;
        // F: bf16 Dekker pre-pack
        uint32_t h0,l0,h1,l1,h2,l2,h3,l3;
        pack_split(f[0], f[1], h0, l0);
        pack_split(f[2], f[3], h1, l1);
        pack_split(f[4], f[5], h2, l2);
        pack_split(f[6], f[7], h3, l3);
        uint4* fp = (uint4*)&d_fpk[bn * 8];
        fp[0] = make_uint4(h0, h1, h2, h3);
        fp[1] = make_uint4(l0, l1, l2, l3);
        // H: fp16 transposed
        #pragma unroll
        for (int e = 0; e < 8; e++)
            d_hT[(size_t)e * BN + bn] = f2h(h[e]);
        // G: f32
        float4* gp = (float4*)&d_g[bn * 8];
        gp[0] = make_float4(g[0], g[1], g[2], g[3]);
        gp[1] = make_float4(g[4], g[5], g[6], g[7]);
    }
}

// ---------------- Kernel B: FA2-style HMMA attention ----------------------
// grid (KSPLIT, Nn/128, Bb), block 128 (4 warps, 32 queries each).
// All-MUFU exp (R11 config); launch_bounds caps regs for 6 CTAs/SM.
__global__ __launch_bounds__(128, 6) void attn_kernel()
{
    __shared__ __align__(16) uint32_t s_fh[2][CHK * 4];   // f_hi bf16x2: [key][4]
    __shared__ __align__(16) uint32_t s_fl[2][CHK * 4];   // f_lo
    __shared__ __align__(16) uint32_t s_hT[2][8 * 132];   // H^T fp16x2: 8 rows, 132 u32 stride

    const int t = threadIdx.x, wid = t >> 5, lane = t & 31;
    const int ks = blockIdx.x, qt = blockIdx.y, b = blockIdx.z;
    const int kbase = ks * KPC;
    const int r = lane >> 2, c2 = (lane & 3) * 2;
    const uint32_t ONES = 0x3C003C00u;   // fp16x2 {1,1}

    // G A-fragments (once): A[16q x 16] = [g_hi(8) | g_lo(8)] bf16
    uint32_t aG[2][4];
    #pragma unroll
    for (int mt = 0; mt < 2; mt++) {
        #pragma unroll
        for (int hh = 0; hh < 2; hh++) {
            const int q = qt * 128 + wid * 32 + mt * 16 + r + hh * 8;
            const float2 gv = *(const float2*)&d_g[((size_t)b * Nn + q) * 8 + c2];
            uint32_t hw, lw;
            pack_split(gv.x, gv.y, hw, lw);
            aG[mt][hh]     = hw;
            aG[mt][2 + hh] = lw;
        }
    }

    float vacc[2][4] = {{0.f,0.f,0.f,0.f},{0.f,0.f,0.f,0.f}};
    float dacc[2][4] = {{0.f,0.f,0.f,0.f},{0.f,0.f,0.f,0.f}};

    auto load_chunk = [&](int ch, int buf) {
        const size_t base = (size_t)b * Nn + kbase + ch * CHK;
        // F: keys t, t+128 — straight uint4 copies
        #pragma unroll
        for (int kk = 0; kk < 2; kk++) {
            const int key = t + kk * 128;
            const uint4* src = (const uint4*)&d_fpk[(base + key) * 8];
            *(uint4*)&s_fh[buf][key * 4] = src[0];
            *(uint4*)&s_fl[buf][key * 4] = src[1];
        }
        // H^T: 8 rows x 128 u32; thread t -> row t>>4, words (t&15)*8 .. +8
        {
            const int d = t >> 4, w = (t & 15) * 8;
            const uint4* hs = (const uint4*)((const uint32_t*)d_hT +
                                             (((size_t)d * BN + base) >> 1) + w);
            *(uint4*)&s_hT[buf][d * 132 + w]     = hs[0];
            *(uint4*)&s_hT[buf][d * 132 + w + 4] = hs[1];
        }
    };

    auto compute = [&](int buf) {
        #pragma unroll
        for (int g = 0; g < 16; g++) {         // 16-key groups
            #pragma unroll
            for (int mt = 0; mt < 2; mt++) {
                // S: two n8 tiles, exact via bf16 hi+lo; acc pre-biased -SHIFT
                float s[8] = {-SHIFT,-SHIFT,-SHIFT,-SHIFT,-SHIFT,-SHIFT,-SHIFT,-SHIFT};
                #pragma unroll
                for (int nt = 0; nt < 2; nt++) {
                    const int key = g * 16 + nt * 8 + r;
                    const uint32_t bh = s_fh[buf][key * 4 + (lane & 3)];
                    const uint32_t bl = s_fl[buf][key * 4 + (lane & 3)];
                    mma16816(&s[nt * 4], aG[mt], bh, bh);  // (gh+gl)*fh
                    mma16816(&s[nt * 4], aG[mt], bl, bl);  // (gh+gl)*fl
                }
                // p = 2^s (shift folded into accumulator bias)
                float p[8];
                #pragma unroll
                for (int j = 0; j < 8; j++) p[j] = ex2f(s[j]);
                // P A-fragment, fp16 satfinite
                uint32_t ap[4];
                ap[0] = pkf16s(p[0], p[1]);
                ap[1] = pkf16s(p[2], p[3]);
                ap[2] = pkf16s(p[4], p[5]);
                ap[3] = pkf16s(p[6], p[7]);
                // V: single fp16 MMA over 16 keys
                const int kw = g * 8 + (lane & 3);
                const uint32_t b0 = s_hT[buf][r * 132 + kw];
                const uint32_t b1 = s_hT[buf][r * 132 + kw + 4];
                mma16816h(vacc[mt], ap, b0, b1);
                // den: P row-sum via ones-B MMA (tensor pipe)
                mma16816h(dacc[mt], ap, ONES, ONES);
            }
        }
    };

    load_chunk(0, 0);
    __syncthreads();
    for (int ch = 0; ch < NCHK; ch++) {
        if (ch + 1 < NCHK) load_chunk(ch + 1, (ch + 1) & 1);  // LDGs overlap compute
        compute(ch & 1);
        __syncthreads();
    }

    // Epilogue: dacc holds full row-sums (all cols identical)
    const size_t base = ((size_t)ks * Bb + b) * Nn;
    #pragma unroll
    for (int mt = 0; mt < 2; mt++) {
        #pragma unroll
        for (int hh = 0; hh < 2; hh++) {
            const int q = qt * 128 + wid * 32 + mt * 16 + r + hh * 8;
            *(float2*)&d_pacc[(base + q) * 8 + c2] =
                make_float2(vacc[mt][2 * hh], vacc[mt][2 * hh + 1]);
            if ((lane & 3) == 0) d_pden[base + q] = dacc[mt][2 * hh];
        }
    }
}

// ---------------- Kernel C: combine splits, Wo projection, y ---------------
// grid (Nn/128, Bb), block 256: both halves combine 2 splits each.
__global__ __launch_bounds__(256) void out_kernel(
    const float* __restrict__ x,
    const float* __restrict__ Wo, const float* __restrict__ bo,
    const float* __restrict__ gamma, float* __restrict__ out)
{
    __shared__ float vs[8 * 128];
    __shared__ float red2[9][128];
    __shared__ float wos[512], bos[64];
    const int t = threadIdx.x, px = t & 127, half = t >> 7;
    const int b = blockIdx.y;
    const int m = blockIdx.x * 128 + px;

    for (int i = t; i < 512; i += 256) wos[i] = Wo[i];
    if (t < 64) bos[t] = bo[t];

    float acc[8] = {0, 0, 0, 0, 0, 0, 0, 0};
    float den = 0.0f;
    #pragma unroll
    for (int si = 0; si < 2; si++) {
        const int s = half * 2 + si;
        const size_t base = ((size_t)s * Bb + b) * Nn + m;
        const float4* pp = (const float4*)&d_pacc[base * 8];
        const float4 a0 = pp[0], a1 = pp[1];
        acc[0] += a0.x; acc[1] += a0.y; acc[2] += a0.z; acc[3] += a0.w;
        acc[4] += a1.x; acc[5] += a1.y; acc[6] += a1.z; acc[7] += a1.w;
        den += d_pden[base];
    }
    if (half == 1) {
        #pragma unroll
        for (int e = 0; e < 8; e++) red2[e][px] = acc[e];
        red2[8][px] = den;
    }
    __syncthreads();
    if (half == 0) {
        den += red2[8][px];
        const float inv = 1.0f / den;
        #pragma unroll
        for (int e = 0; e < 8; e++)
            vs[e * 128 + px] = (acc[e] + red2[e][px]) * inv;
    }
    __syncthreads();

    const float gam = gamma[0];
    #pragma unroll 4
    for (int ci = 0; ci < 32; ci++) {
        const int c = half * 32 + ci;
        float o = bos[c];
        #pragma unroll
        for (int e = 0; e < 8; e++) o = fmaf(wos[c * 8 + e], vs[e * 128 + px], o);
        const size_t idx = ((size_t)b * 64 + c) * Nn + m;
        out[BCN + idx] = o;
        out[idx]       = fmaf(gam, o, x[idx]);
    }
    if (b == 0 && m == 0 && half == 0) out[2 * BCN] = gam;
}

// ---------------- Launch ----------------------------------------------------
extern "C" void kernel_launch(void* const* d_in, const int* in_sizes, int n_in,
                              void* d_out, int out_size)
{
    const float* x     = (const float*)d_in[0];
    const float* Wk    = (const float*)d_in[1];
    const float* bk    = (const float*)d_in[2];
    const float* Wq    = (const float*)d_in[3];
    const float* bq    = (const float*)d_in[4];
    const float* Wv    = (const float*)d_in[5];
    const float* bv    = (const float*)d_in[6];
    const float* Wo    = (const float*)d_in[7];
    const float* bo    = (const float*)d_in[8];
    const float* gamma = (const float*)d_in[9];
    float* out = (float*)d_out;

    proj_kernel<<<dim3(Nn / 64, Bb), 256>>>(x, Wk, bk, Wq, bq, Wv, bv);
    attn_kernel<<<dim3(KSPLIT, Nn / 128, Bb), 128>>>();
    out_kernel<<<dim3(Nn / 128, Bb), 256>>>(x, Wo, bo, gamma, out);
}